// round 9
// baseline (speedup 1.0000x reference)
#include <cuda_runtime.h>
#include <cuda_bf16.h>
#include <cstddef>
#include <cstdint>

#define DIMC   384
#define HEADS  12
#define HD     32
#define NTOK   256
#define BATCH  256
#define BHTOT  (BATCH * HEADS)      // 3072
#define MTOT   (BATCH * NTOK)       // 65536
#define KWIN   5
#define EPS    1e-6f
#define KEXT   (3 * DIMC)           // 1152: [hi | lo | hi] x [hi | hi | lo]

// ---------------- scratch (device globals: allocation-free) ----------------
__device__ float g_q[(size_t)BHTOT * NTOK * HD];
__device__ float g_k[(size_t)BHTOT * NTOK * HD];
__device__ float g_v[(size_t)BHTOT * NTOK * HD];

__device__ __nv_bfloat16 g_ae[(size_t)MTOT * KEXT];       // x_ext then y_ext
__device__ __nv_bfloat16 g_we[(size_t)(3 * DIMC) * KEXT]; // qkv_w extended
__device__ __nv_bfloat16 g_pe[(size_t)DIMC * KEXT];       // proj_w extended

// ---------------- PTX helpers ----------------------------------------------
#define LDSM_X4(r0, r1, r2, r3, addr) \
    asm volatile("ldmatrix.sync.aligned.m8n8.x4.shared.b16 {%0,%1,%2,%3}, [%4];" \
        : "=r"(r0), "=r"(r1), "=r"(r2), "=r"(r3) : "r"(addr))

#define MMA_BF16(c, a, b0, b1) \
    asm volatile("mma.sync.aligned.m16n8k16.row.col.f32.bf16.bf16.f32 " \
        "{%0,%1,%2,%3}, {%4,%5,%6,%7}, {%8,%9}, {%0,%1,%2,%3};" \
        : "+f"(c[0]), "+f"(c[1]), "+f"(c[2]), "+f"(c[3]) \
        : "r"(a[0]), "r"(a[1]), "r"(a[2]), "r"(a[3]), "r"(b0), "r"(b1))

// ---------------- fp32 -> bf16 hi/lo extended conversions -------------------
// A-style: [hi | lo | hi]   (activations)
__global__ void __launch_bounds__(256) cvt_A_ext(
    const float* __restrict__ src, __nv_bfloat16* __restrict__ dst, int nquads)
{
    int i = blockIdx.x * blockDim.x + threadIdx.x;
    if (i >= nquads) return;
    float4 v = *(const float4*)&src[(size_t)i * 4];
    int row = (i * 4) / DIMC;
    int k   = (i * 4) % DIMC;
    __nv_bfloat16 h[4], l[4];
    float vv[4] = {v.x, v.y, v.z, v.w};
#pragma unroll
    for (int j = 0; j < 4; j++) {
        h[j] = __float2bfloat16(vv[j]);
        l[j] = __float2bfloat16(vv[j] - __bfloat162float(h[j]));
    }
    size_t base = (size_t)row * KEXT;
    uint2 hp, lp;
    ((__nv_bfloat16*)&hp)[0] = h[0]; ((__nv_bfloat16*)&hp)[1] = h[1];
    ((__nv_bfloat16*)&hp)[2] = h[2]; ((__nv_bfloat16*)&hp)[3] = h[3];
    ((__nv_bfloat16*)&lp)[0] = l[0]; ((__nv_bfloat16*)&lp)[1] = l[1];
    ((__nv_bfloat16*)&lp)[2] = l[2]; ((__nv_bfloat16*)&lp)[3] = l[3];
    *(uint2*)&dst[base + k]            = hp;
    *(uint2*)&dst[base + DIMC + k]     = lp;
    *(uint2*)&dst[base + 2 * DIMC + k] = hp;
}

// W-style: [hi | hi | lo]   (weights)
__global__ void __launch_bounds__(256) cvt_W_ext(
    const float* __restrict__ src, __nv_bfloat16* __restrict__ dst, int nquads)
{
    int i = blockIdx.x * blockDim.x + threadIdx.x;
    if (i >= nquads) return;
    float4 v = *(const float4*)&src[(size_t)i * 4];
    int row = (i * 4) / DIMC;
    int k   = (i * 4) % DIMC;
    __nv_bfloat16 h[4], l[4];
    float vv[4] = {v.x, v.y, v.z, v.w};
#pragma unroll
    for (int j = 0; j < 4; j++) {
        h[j] = __float2bfloat16(vv[j]);
        l[j] = __float2bfloat16(vv[j] - __bfloat162float(h[j]));
    }
    size_t base = (size_t)row * KEXT;
    uint2 hp, lp;
    ((__nv_bfloat16*)&hp)[0] = h[0]; ((__nv_bfloat16*)&hp)[1] = h[1];
    ((__nv_bfloat16*)&hp)[2] = h[2]; ((__nv_bfloat16*)&hp)[3] = h[3];
    ((__nv_bfloat16*)&lp)[0] = l[0]; ((__nv_bfloat16*)&lp)[1] = l[1];
    ((__nv_bfloat16*)&lp)[2] = l[2]; ((__nv_bfloat16*)&lp)[3] = l[3];
    *(uint2*)&dst[base + k]            = hp;
    *(uint2*)&dst[base + DIMC + k]     = hp;
    *(uint2*)&dst[base + 2 * DIMC + k] = lp;
}

// ---------------- bf16 tensor-core GEMM ------------------------------------
// C[m][n] = sum_k' Aext[m][k'] * Wext[n][k'], k' = 1152. BM=BN=128, BK=32.
// 4 warps (128 thr): warp grid 2(m) x 2(n), warp tile 64x64 — halves the
// cross-warp LDSM redundancy vs the 8-warp 64x32 layout (L1 was 91% busy).
// EPI=0: qkv epilogue (bias, relu, +pos_enc, head scatter to g_q/g_k/g_v)
// EPI=1: proj epilogue (bias, store fp32 out)
#define BKB 32
#define APITCH 40   // 32 + 8 pad (bf16) -> 80B row, conflict-free LDSM

template <int EPI>
__global__ void __launch_bounds__(128, 2) gemm_bf16(
    const __nv_bfloat16* __restrict__ Aext, const __nv_bfloat16* __restrict__ Wext,
    const float* __restrict__ bias, const float* __restrict__ pos_enc,
    float* __restrict__ Cout)
{
    __shared__ __nv_bfloat16 As[2][128][APITCH];
    __shared__ __nv_bfloat16 Bs[2][128][APITCH];

    const int tid  = threadIdx.x;
    const int lane = tid & 31;
    const int warp = tid >> 5;
    const int wm = warp >> 1;      // 0..1
    const int wn = warp & 1;       // 0..1
    const int bm = blockIdx.y * 128;
    const int bn = blockIdx.x * 128;

    // gmem load coords: 4 int4 (8 bf16) each for A and B per k-tile
    int lrow[4], lch[4];
#pragma unroll
    for (int l = 0; l < 4; l++) {
        int idx = tid + l * 128;       // 0..511
        lrow[l] = idx >> 2;
        lch[l] = idx & 3;
    }

    float acc[4][8][4];
#pragma unroll
    for (int mt = 0; mt < 4; mt++)
#pragma unroll
        for (int nt = 0; nt < 8; nt++)
#pragma unroll
            for (int e = 0; e < 4; e++) acc[mt][nt][e] = 0.f;

    int4 pa[4], pb[4];
    // prologue: tile 0
#pragma unroll
    for (int l = 0; l < 4; l++) {
        pa[l] = *(const int4*)&Aext[(size_t)(bm + lrow[l]) * KEXT + lch[l] * 8];
        pb[l] = *(const int4*)&Wext[(size_t)(bn + lrow[l]) * KEXT + lch[l] * 8];
    }
#pragma unroll
    for (int l = 0; l < 4; l++) {
        *(int4*)&As[0][lrow[l]][lch[l] * 8] = pa[l];
        *(int4*)&Bs[0][lrow[l]][lch[l] * 8] = pb[l];
    }
    __syncthreads();

    const int nkt = KEXT / BKB;   // 36
    for (int kt = 0; kt < nkt; kt++) {
        const int cur = kt & 1;
        const bool has_next = (kt + 1 < nkt);
        if (has_next) {
            int ko = (kt + 1) * BKB;
#pragma unroll
            for (int l = 0; l < 4; l++) {
                pa[l] = *(const int4*)&Aext[(size_t)(bm + lrow[l]) * KEXT + ko + lch[l] * 8];
                pb[l] = *(const int4*)&Wext[(size_t)(bn + lrow[l]) * KEXT + ko + lch[l] * 8];
            }
        }

#pragma unroll
        for (int s = 0; s < 2; s++) {       // two k16 steps
            uint32_t a[4][4];
#pragma unroll
            for (int mt = 0; mt < 4; mt++) {
                int r = wm * 64 + mt * 16 + (lane & 15);
                int c = s * 16 + ((lane >> 4) << 3);
                uint32_t ad = (uint32_t)__cvta_generic_to_shared(&As[cur][r][c]);
                LDSM_X4(a[mt][0], a[mt][1], a[mt][2], a[mt][3], ad);
            }
            uint32_t b[8][2];
#pragma unroll
            for (int nt2 = 0; nt2 < 4; nt2++) {
                int r = wn * 64 + nt2 * 16 + ((lane >> 4) << 3) + (lane & 7);
                int c = s * 16 + (((lane >> 3) & 1) << 3);
                uint32_t ad = (uint32_t)__cvta_generic_to_shared(&Bs[cur][r][c]);
                LDSM_X4(b[nt2 * 2][0], b[nt2 * 2][1],
                        b[nt2 * 2 + 1][0], b[nt2 * 2 + 1][1], ad);
            }
#pragma unroll
            for (int mt = 0; mt < 4; mt++)
#pragma unroll
                for (int nt = 0; nt < 8; nt++)
                    MMA_BF16(acc[mt][nt], a[mt], b[nt][0], b[nt][1]);
        }

        if (has_next) {
            const int nxt = cur ^ 1;
#pragma unroll
            for (int l = 0; l < 4; l++) {
                *(int4*)&As[nxt][lrow[l]][lch[l] * 8] = pa[l];
                *(int4*)&Bs[nxt][lrow[l]][lch[l] * 8] = pb[l];
            }
        }
        __syncthreads();
    }

    // ---- epilogue ----
    if (EPI == 0) {
#pragma unroll
        for (int mt = 0; mt < 4; mt++) {
            int m0 = bm + wm * 64 + mt * 16 + (lane >> 2);
#pragma unroll
            for (int nt = 0; nt < 8; nt++) {
                int n0 = bn + wn * 64 + nt * 8 + (lane & 3) * 2;
#pragma unroll
                for (int e = 0; e < 4; e++) {
                    int m = m0 + (e >> 1) * 8;
                    int n = n0 + (e & 1);
                    int b = m >> 8;
                    int i = m & 255;
                    float val = acc[mt][nt][e] + bias[n];
                    int region = n / DIMC;
                    int ch = n - region * DIMC;
                    int h = ch >> 5;
                    int d = ch & 31;
                    size_t dst = ((size_t)(b * HEADS + h) * NTOK + i) * HD + d;
                    if (region == 0) {
                        g_q[dst] = fmaxf(val, 0.f);
                    } else if (region == 1) {
                        g_k[dst] = fmaxf(val + pos_enc[(size_t)i * DIMC + ch], 0.f);
                    } else {
                        g_v[dst] = val;
                    }
                }
            }
        }
    } else {
#pragma unroll
        for (int mt = 0; mt < 4; mt++) {
            int m0 = bm + wm * 64 + mt * 16 + (lane >> 2);
#pragma unroll
            for (int nt = 0; nt < 8; nt++) {
                int n0 = bn + wn * 64 + nt * 8 + (lane & 3) * 2;
                float2 lo, hi2;
                lo.x  = acc[mt][nt][0] + bias[n0];
                lo.y  = acc[mt][nt][1] + bias[n0 + 1];
                hi2.x = acc[mt][nt][2] + bias[n0];
                hi2.y = acc[mt][nt][3] + bias[n0 + 1];
                *(float2*)&Cout[(size_t)m0 * DIMC + n0] = lo;
                *(float2*)&Cout[(size_t)(m0 + 8) * DIMC + n0] = hi2;
            }
        }
    }
}

// ---------------- fused linear attention + depthwise conv ------------------
// Output epilogue writes the hi/lo/hi bf16 extended row for the proj GEMM
// directly into g_ae (reusing the x_ext buffer — gemm<0> has consumed it).
#define SM_Q   0
#define SM_K   (256 * 33)
#define SM_V   (2 * 256 * 33)
#define SM_KV  (3 * 256 * 33)          // 25344
#define SM_KS  (SM_KV + 32 * 33)       // 26400
#define SM_W   (SM_KS + 32)            // 26432
#define SM_B   (SM_W + 800)            // 27232
#define SM_FLOATS (SM_B + 32)          // 27264
#define SMEM_BYTES (SM_FLOATS * 4)     // 109056

__global__ void __launch_bounds__(256) attn_kernel(
    const float* __restrict__ dwc_w, const float* __restrict__ dwc_b)
{
    extern __shared__ float sm[];
    float* qs   = sm + SM_Q;
    float* ks   = sm + SM_K;
    float* vs   = sm + SM_V;
    float* kvs  = sm + SM_KV;
    float* ksum = sm + SM_KS;
    float* ws   = sm + SM_W;
    float* bsm  = sm + SM_B;

    const int tid = threadIdx.x;
    const int bh = blockIdx.x;
    const size_t base = (size_t)bh * (NTOK * HD);

    for (int idx = tid; idx < 2048; idx += 256) {
        int row = idx >> 3;
        int col = (idx & 7) * 4;
        float4 t;
        t = *(const float4*)&g_q[base + row * 32 + col];
        qs[row * 33 + col] = t.x; qs[row * 33 + col + 1] = t.y;
        qs[row * 33 + col + 2] = t.z; qs[row * 33 + col + 3] = t.w;
        t = *(const float4*)&g_k[base + row * 32 + col];
        ks[row * 33 + col] = t.x; ks[row * 33 + col + 1] = t.y;
        ks[row * 33 + col + 2] = t.z; ks[row * 33 + col + 3] = t.w;
        t = *(const float4*)&g_v[base + row * 32 + col];
        vs[row * 33 + col] = t.x; vs[row * 33 + col + 1] = t.y;
        vs[row * 33 + col + 2] = t.z; vs[row * 33 + col + 3] = t.w;
    }
    for (int idx = tid; idx < 800; idx += 256) ws[idx] = dwc_w[idx];
    if (tid < 32) bsm[tid] = dwc_b[tid];
    __syncthreads();

    {
        const int c = tid >> 3;
        const int d0 = tid & 7;
        float a0 = 0.f, a1 = 0.f, a2 = 0.f, a3 = 0.f, s = 0.f;
#pragma unroll 4
        for (int j = 0; j < 256; j++) {
            float kk = ks[j * 33 + c];
            a0 += kk * vs[j * 33 + d0];
            a1 += kk * vs[j * 33 + d0 + 8];
            a2 += kk * vs[j * 33 + d0 + 16];
            a3 += kk * vs[j * 33 + d0 + 24];
            s += kk;
        }
        kvs[c * 33 + d0]      = a0;
        kvs[c * 33 + d0 + 8]  = a1;
        kvs[c * 33 + d0 + 16] = a2;
        kvs[c * 33 + d0 + 24] = a3;
        if (d0 == 0) ksum[c] = s;
    }
    __syncthreads();

    const int i = tid;
    float qr[32];
#pragma unroll
    for (int c = 0; c < 32; c++) qr[c] = qs[i * 33 + c];

    float zden = EPS;
#pragma unroll
    for (int c = 0; c < 32; c++) zden += qr[c] * ksum[c];
    const float z = 1.0f / zden;

    float acc[32];
#pragma unroll
    for (int d = 0; d < 32; d++) acc[d] = 0.f;
#pragma unroll
    for (int c = 0; c < 32; c++) {
        float qc = qr[c];
#pragma unroll
        for (int d = 0; d < 32; d++) acc[d] += qc * kvs[c * 33 + d];
    }
#pragma unroll
    for (int d = 0; d < 32; d++) acc[d] *= z;

    const int a = i >> 4;
    const int b_s = i & 15;
#pragma unroll
    for (int ka = 0; ka < KWIN; ka++) {
        int aa = a + ka - 2;
        if (aa < 0 || aa > 15) continue;
#pragma unroll
        for (int kb = 0; kb < KWIN; kb++) {
            int bb = b_s + kb - 2;
            if (bb < 0 || bb > 15) continue;
            int nn = aa * 16 + bb;
#pragma unroll
            for (int d = 0; d < 32; d++)
                acc[d] += vs[nn * 33 + d] * ws[d * 25 + ka * KWIN + kb];
        }
    }
#pragma unroll
    for (int d = 0; d < 32; d++) acc[d] += bsm[d];

    // epilogue: hi/lo split, write extended bf16 row segment for proj GEMM
    const int b = bh / HEADS;
    const int h = bh - b * HEADS;
    __nv_bfloat16 hbuf[32], lbuf[32];
#pragma unroll
    for (int d = 0; d < 32; d++) {
        hbuf[d] = __float2bfloat16(acc[d]);
        lbuf[d] = __float2bfloat16(acc[d] - __bfloat162float(hbuf[d]));
    }
    __nv_bfloat16* dst = g_ae + ((size_t)(b * NTOK + i)) * KEXT + h * HD;
#pragma unroll
    for (int j = 0; j < 4; j++) {
        uint4 hp = ((const uint4*)hbuf)[j];
        uint4 lp = ((const uint4*)lbuf)[j];
        *(uint4*)&dst[j * 8]            = hp;   // seg 0: hi
        *(uint4*)&dst[DIMC + j * 8]     = lp;   // seg 1: lo
        *(uint4*)&dst[2 * DIMC + j * 8] = hp;   // seg 2: hi
    }
}

// ---------------- launch ----------------------------------------------------
extern "C" void kernel_launch(void* const* d_in, const int* in_sizes, int n_in,
                              void* d_out, int out_size)
{
    const float* x       = (const float*)d_in[0];
    const float* qkv_w   = (const float*)d_in[1];
    const float* qkv_b   = (const float*)d_in[2];
    const float* pos_enc = (const float*)d_in[3];
    const float* dwc_w   = (const float*)d_in[4];
    const float* dwc_b   = (const float*)d_in[5];
    const float* proj_w  = (const float*)d_in[6];
    const float* proj_b  = (const float*)d_in[7];
    float* out = (float*)d_out;

    cudaFuncSetAttribute(attn_kernel,
                         cudaFuncAttributeMaxDynamicSharedMemorySize, SMEM_BYTES);

    __nv_bfloat16* ae; cudaGetSymbolAddress((void**)&ae, g_ae);
    __nv_bfloat16* we; cudaGetSymbolAddress((void**)&we, g_we);
    __nv_bfloat16* pe; cudaGetSymbolAddress((void**)&pe, g_pe);

    // 0) conversions: x, qkv_w, proj_w -> bf16 hi/lo extended
    {
        int nq = MTOT * DIMC / 4;
        cvt_A_ext<<<(nq + 255) / 256, 256>>>(x, ae, nq);
        int nw = 3 * DIMC * DIMC / 4;
        cvt_W_ext<<<(nw + 255) / 256, 256>>>(qkv_w, we, nw);
        int np = DIMC * DIMC / 4;
        cvt_W_ext<<<(np + 255) / 256, 256>>>(proj_w, pe, np);
    }

    // 1) qkv GEMM (bf16 TC) + fused epilogue -> g_q/g_k/g_v
    gemm_bf16<0><<<dim3((3 * DIMC) / 128, MTOT / 128), 128>>>(
        ae, we, qkv_b, pos_enc, nullptr);

    // 2) fused linear attention + depthwise conv -> y_ext (reuses g_ae)
    attn_kernel<<<BHTOT, 256, SMEM_BYTES>>>(dwc_w, dwc_b);

    // 3) proj GEMM (bf16 TC) -> out
    gemm_bf16<1><<<dim3(DIMC / 128, MTOT / 128), 128>>>(
        ae, pe, proj_b, nullptr, out);
}

// round 10
// speedup vs baseline: 1.2781x; 1.2781x over previous
#include <cuda_runtime.h>
#include <cuda_fp16.h>
#include <cstddef>
#include <cstdint>

#define DIMC   384
#define HEADS  12
#define HD     32
#define NTOK   256
#define BATCH  256
#define BHTOT  (BATCH * HEADS)      // 3072
#define MTOT   (BATCH * NTOK)       // 65536
#define KWIN   5
#define EPS    1e-6f
#define KEXT   (2 * DIMC)           // 768: A=[hi|lo], W=[hi|hi] (fp16 split)

// ---------------- scratch (device globals: allocation-free) ----------------
__device__ float g_q[(size_t)BHTOT * NTOK * HD];
__device__ float g_k[(size_t)BHTOT * NTOK * HD];
__device__ float g_v[(size_t)BHTOT * NTOK * HD];

__device__ __half g_ae[(size_t)MTOT * KEXT];       // x_ext then y_ext (100 MB)
__device__ __half g_we[(size_t)(3 * DIMC) * KEXT]; // qkv_w extended
__device__ __half g_pe[(size_t)DIMC * KEXT];       // proj_w extended

// ---------------- PTX helpers ----------------------------------------------
#define LDSM_X4(r0, r1, r2, r3, addr) \
    asm volatile("ldmatrix.sync.aligned.m8n8.x4.shared.b16 {%0,%1,%2,%3}, [%4];" \
        : "=r"(r0), "=r"(r1), "=r"(r2), "=r"(r3) : "r"(addr))

#define MMA_F16(c, a, b0, b1) \
    asm volatile("mma.sync.aligned.m16n8k16.row.col.f32.f16.f16.f32 " \
        "{%0,%1,%2,%3}, {%4,%5,%6,%7}, {%8,%9}, {%0,%1,%2,%3};" \
        : "+f"(c[0]), "+f"(c[1]), "+f"(c[2]), "+f"(c[3]) \
        : "r"(a[0]), "r"(a[1]), "r"(a[2]), "r"(a[3]), "r"(b0), "r"(b1))

// ---------------- fp32 -> fp16 hi/lo extended conversions -------------------
// A-style: [hi | lo]   (activations; hi+lo == value to ~2^-22)
__global__ void __launch_bounds__(256) cvt_A_ext(
    const float* __restrict__ src, __half* __restrict__ dst, int nquads)
{
    int i = blockIdx.x * blockDim.x + threadIdx.x;
    if (i >= nquads) return;
    float4 v = *(const float4*)&src[(size_t)i * 4];
    int row = (i * 4) / DIMC;
    int k   = (i * 4) % DIMC;
    __half h[4], l[4];
    float vv[4] = {v.x, v.y, v.z, v.w};
#pragma unroll
    for (int j = 0; j < 4; j++) {
        h[j] = __float2half(vv[j]);
        l[j] = __float2half(vv[j] - __half2float(h[j]));
    }
    size_t base = (size_t)row * KEXT;
    uint2 hp, lp;
    ((__half*)&hp)[0] = h[0]; ((__half*)&hp)[1] = h[1];
    ((__half*)&hp)[2] = h[2]; ((__half*)&hp)[3] = h[3];
    ((__half*)&lp)[0] = l[0]; ((__half*)&lp)[1] = l[1];
    ((__half*)&lp)[2] = l[2]; ((__half*)&lp)[3] = l[3];
    *(uint2*)&dst[base + k]        = hp;
    *(uint2*)&dst[base + DIMC + k] = lp;
}

// W-style: [hi | hi]   (weights; rounding error -> A·W_lo term, ~2^-11 rel)
__global__ void __launch_bounds__(256) cvt_W_ext(
    const float* __restrict__ src, __half* __restrict__ dst, int nquads)
{
    int i = blockIdx.x * blockDim.x + threadIdx.x;
    if (i >= nquads) return;
    float4 v = *(const float4*)&src[(size_t)i * 4];
    int row = (i * 4) / DIMC;
    int k   = (i * 4) % DIMC;
    __half h[4];
    float vv[4] = {v.x, v.y, v.z, v.w};
#pragma unroll
    for (int j = 0; j < 4; j++) h[j] = __float2half(vv[j]);
    size_t base = (size_t)row * KEXT;
    uint2 hp;
    ((__half*)&hp)[0] = h[0]; ((__half*)&hp)[1] = h[1];
    ((__half*)&hp)[2] = h[2]; ((__half*)&hp)[3] = h[3];
    *(uint2*)&dst[base + k]        = hp;
    *(uint2*)&dst[base + DIMC + k] = hp;
}

// ---------------- fp16 tensor-core GEMM (R7 structure) ----------------------
// C[m][n] = sum_k' Aext[m][k'] * Wext[n][k'], k' = 768. BM=BN=128, BK=32.
// 8 warps: warp grid 2(m) x 4(n), warp tile 64x32, mma m16n8k16.
#define BKB 32
#define APITCH 40   // 32 + 8 pad (fp16) -> 80B row, conflict-free LDSM

template <int EPI>
__global__ void __launch_bounds__(256, 2) gemm_f16(
    const __half* __restrict__ Aext, const __half* __restrict__ Wext,
    const float* __restrict__ bias, const float* __restrict__ pos_enc,
    float* __restrict__ Cout)
{
    __shared__ __half As[2][128][APITCH];
    __shared__ __half Bs[2][128][APITCH];

    const int tid  = threadIdx.x;
    const int lane = tid & 31;
    const int warp = tid >> 5;
    const int wm = warp >> 2;      // 0..1
    const int wn = warp & 3;       // 0..3
    const int bm = blockIdx.y * 128;
    const int bn = blockIdx.x * 128;

    int lrow[2], lch[2];
#pragma unroll
    for (int l = 0; l < 2; l++) {
        int idx = tid + l * 256;
        lrow[l] = idx >> 2;
        lch[l] = idx & 3;
    }

    float acc[4][4][4];
#pragma unroll
    for (int mt = 0; mt < 4; mt++)
#pragma unroll
        for (int nt = 0; nt < 4; nt++)
#pragma unroll
            for (int e = 0; e < 4; e++) acc[mt][nt][e] = 0.f;

    int4 pa[2], pb[2];
#pragma unroll
    for (int l = 0; l < 2; l++) {
        pa[l] = *(const int4*)&Aext[(size_t)(bm + lrow[l]) * KEXT + lch[l] * 8];
        pb[l] = *(const int4*)&Wext[(size_t)(bn + lrow[l]) * KEXT + lch[l] * 8];
    }
#pragma unroll
    for (int l = 0; l < 2; l++) {
        *(int4*)&As[0][lrow[l]][lch[l] * 8] = pa[l];
        *(int4*)&Bs[0][lrow[l]][lch[l] * 8] = pb[l];
    }
    __syncthreads();

    const int nkt = KEXT / BKB;   // 24
    for (int kt = 0; kt < nkt; kt++) {
        const int cur = kt & 1;
        const bool has_next = (kt + 1 < nkt);
        if (has_next) {
            int ko = (kt + 1) * BKB;
#pragma unroll
            for (int l = 0; l < 2; l++) {
                pa[l] = *(const int4*)&Aext[(size_t)(bm + lrow[l]) * KEXT + ko + lch[l] * 8];
                pb[l] = *(const int4*)&Wext[(size_t)(bn + lrow[l]) * KEXT + ko + lch[l] * 8];
            }
        }

#pragma unroll
        for (int s = 0; s < 2; s++) {       // two k16 steps
            uint32_t a[4][4];
#pragma unroll
            for (int mt = 0; mt < 4; mt++) {
                int r = wm * 64 + mt * 16 + (lane & 15);
                int c = s * 16 + ((lane >> 4) << 3);
                uint32_t ad = (uint32_t)__cvta_generic_to_shared(&As[cur][r][c]);
                LDSM_X4(a[mt][0], a[mt][1], a[mt][2], a[mt][3], ad);
            }
            uint32_t b[4][2];
#pragma unroll
            for (int nt2 = 0; nt2 < 2; nt2++) {
                int r = wn * 32 + nt2 * 16 + ((lane >> 4) << 3) + (lane & 7);
                int c = s * 16 + (((lane >> 3) & 1) << 3);
                uint32_t ad = (uint32_t)__cvta_generic_to_shared(&Bs[cur][r][c]);
                LDSM_X4(b[nt2 * 2][0], b[nt2 * 2][1],
                        b[nt2 * 2 + 1][0], b[nt2 * 2 + 1][1], ad);
            }
#pragma unroll
            for (int mt = 0; mt < 4; mt++)
#pragma unroll
                for (int nt = 0; nt < 4; nt++)
                    MMA_F16(acc[mt][nt], a[mt], b[nt][0], b[nt][1]);
        }

        if (has_next) {
            const int nxt = cur ^ 1;
#pragma unroll
            for (int l = 0; l < 2; l++) {
                *(int4*)&As[nxt][lrow[l]][lch[l] * 8] = pa[l];
                *(int4*)&Bs[nxt][lrow[l]][lch[l] * 8] = pb[l];
            }
        }
        __syncthreads();
    }

    // ---- epilogue ----
    if (EPI == 0) {
#pragma unroll
        for (int mt = 0; mt < 4; mt++) {
            int m0 = bm + wm * 64 + mt * 16 + (lane >> 2);
#pragma unroll
            for (int nt = 0; nt < 4; nt++) {
                int n0 = bn + wn * 32 + nt * 8 + (lane & 3) * 2;
#pragma unroll
                for (int e = 0; e < 4; e++) {
                    int m = m0 + (e >> 1) * 8;
                    int n = n0 + (e & 1);
                    int b = m >> 8;
                    int i = m & 255;
                    float val = acc[mt][nt][e] + bias[n];
                    int region = n / DIMC;
                    int ch = n - region * DIMC;
                    int h = ch >> 5;
                    int d = ch & 31;
                    size_t dst = ((size_t)(b * HEADS + h) * NTOK + i) * HD + d;
                    if (region == 0) {
                        g_q[dst] = fmaxf(val, 0.f);
                    } else if (region == 1) {
                        g_k[dst] = fmaxf(val + pos_enc[(size_t)i * DIMC + ch], 0.f);
                    } else {
                        g_v[dst] = val;
                    }
                }
            }
        }
    } else {
#pragma unroll
        for (int mt = 0; mt < 4; mt++) {
            int m0 = bm + wm * 64 + mt * 16 + (lane >> 2);
#pragma unroll
            for (int nt = 0; nt < 4; nt++) {
                int n0 = bn + wn * 32 + nt * 8 + (lane & 3) * 2;
                float2 lo, hi2;
                lo.x  = acc[mt][nt][0] + bias[n0];
                lo.y  = acc[mt][nt][1] + bias[n0 + 1];
                hi2.x = acc[mt][nt][2] + bias[n0];
                hi2.y = acc[mt][nt][3] + bias[n0 + 1];
                *(float2*)&Cout[(size_t)m0 * DIMC + n0] = lo;
                *(float2*)&Cout[(size_t)(m0 + 8) * DIMC + n0] = hi2;
            }
        }
    }
}

// ---------------- fused linear attention + depthwise conv ------------------
// Epilogue writes the [hi|lo] fp16 extended row for the proj GEMM directly
// into g_ae (reusing the x_ext buffer — gemm<0> has consumed it).
#define SM_Q   0
#define SM_K   (256 * 33)
#define SM_V   (2 * 256 * 33)
#define SM_KV  (3 * 256 * 33)          // 25344
#define SM_KS  (SM_KV + 32 * 33)       // 26400
#define SM_W   (SM_KS + 32)            // 26432
#define SM_B   (SM_W + 800)            // 27232
#define SM_FLOATS (SM_B + 32)          // 27264
#define SMEM_BYTES (SM_FLOATS * 4)     // 109056

__global__ void __launch_bounds__(256) attn_kernel(
    const float* __restrict__ dwc_w, const float* __restrict__ dwc_b)
{
    extern __shared__ float sm[];
    float* qs   = sm + SM_Q;
    float* ks   = sm + SM_K;
    float* vs   = sm + SM_V;
    float* kvs  = sm + SM_KV;
    float* ksum = sm + SM_KS;
    float* ws   = sm + SM_W;
    float* bsm  = sm + SM_B;

    const int tid = threadIdx.x;
    const int bh = blockIdx.x;
    const size_t base = (size_t)bh * (NTOK * HD);

    for (int idx = tid; idx < 2048; idx += 256) {
        int row = idx >> 3;
        int col = (idx & 7) * 4;
        float4 t;
        t = *(const float4*)&g_q[base + row * 32 + col];
        qs[row * 33 + col] = t.x; qs[row * 33 + col + 1] = t.y;
        qs[row * 33 + col + 2] = t.z; qs[row * 33 + col + 3] = t.w;
        t = *(const float4*)&g_k[base + row * 32 + col];
        ks[row * 33 + col] = t.x; ks[row * 33 + col + 1] = t.y;
        ks[row * 33 + col + 2] = t.z; ks[row * 33 + col + 3] = t.w;
        t = *(const float4*)&g_v[base + row * 32 + col];
        vs[row * 33 + col] = t.x; vs[row * 33 + col + 1] = t.y;
        vs[row * 33 + col + 2] = t.z; vs[row * 33 + col + 3] = t.w;
    }
    for (int idx = tid; idx < 800; idx += 256) ws[idx] = dwc_w[idx];
    if (tid < 32) bsm[tid] = dwc_b[tid];
    __syncthreads();

    {
        const int c = tid >> 3;
        const int d0 = tid & 7;
        float a0 = 0.f, a1 = 0.f, a2 = 0.f, a3 = 0.f, s = 0.f;
#pragma unroll 4
        for (int j = 0; j < 256; j++) {
            float kk = ks[j * 33 + c];
            a0 += kk * vs[j * 33 + d0];
            a1 += kk * vs[j * 33 + d0 + 8];
            a2 += kk * vs[j * 33 + d0 + 16];
            a3 += kk * vs[j * 33 + d0 + 24];
            s += kk;
        }
        kvs[c * 33 + d0]      = a0;
        kvs[c * 33 + d0 + 8]  = a1;
        kvs[c * 33 + d0 + 16] = a2;
        kvs[c * 33 + d0 + 24] = a3;
        if (d0 == 0) ksum[c] = s;
    }
    __syncthreads();

    const int i = tid;
    float qr[32];
#pragma unroll
    for (int c = 0; c < 32; c++) qr[c] = qs[i * 33 + c];

    float zden = EPS;
#pragma unroll
    for (int c = 0; c < 32; c++) zden += qr[c] * ksum[c];
    const float z = 1.0f / zden;

    float acc[32];
#pragma unroll
    for (int d = 0; d < 32; d++) acc[d] = 0.f;
#pragma unroll
    for (int c = 0; c < 32; c++) {
        float qc = qr[c];
#pragma unroll
        for (int d = 0; d < 32; d++) acc[d] += qc * kvs[c * 33 + d];
    }
#pragma unroll
    for (int d = 0; d < 32; d++) acc[d] *= z;

    const int a = i >> 4;
    const int b_s = i & 15;
#pragma unroll
    for (int ka = 0; ka < KWIN; ka++) {
        int aa = a + ka - 2;
        if (aa < 0 || aa > 15) continue;
#pragma unroll
        for (int kb = 0; kb < KWIN; kb++) {
            int bb = b_s + kb - 2;
            if (bb < 0 || bb > 15) continue;
            int nn = aa * 16 + bb;
#pragma unroll
            for (int d = 0; d < 32; d++)
                acc[d] += vs[nn * 33 + d] * ws[d * 25 + ka * KWIN + kb];
        }
    }
#pragma unroll
    for (int d = 0; d < 32; d++) acc[d] += bsm[d];

    // epilogue: fp16 hi/lo split, write extended row segment for proj GEMM
    const int b = bh / HEADS;
    const int h = bh - b * HEADS;
    __half hbuf[32], lbuf[32];
#pragma unroll
    for (int d = 0; d < 32; d++) {
        hbuf[d] = __float2half(acc[d]);
        lbuf[d] = __float2half(acc[d] - __half2float(hbuf[d]));
    }
    __half* dst = g_ae + ((size_t)(b * NTOK + i)) * KEXT + h * HD;
#pragma unroll
    for (int j = 0; j < 4; j++) {
        uint4 hp = ((const uint4*)hbuf)[j];
        uint4 lp = ((const uint4*)lbuf)[j];
        *(uint4*)&dst[j * 8]        = hp;   // seg 0: hi
        *(uint4*)&dst[DIMC + j * 8] = lp;   // seg 1: lo
    }
}

// ---------------- launch ----------------------------------------------------
extern "C" void kernel_launch(void* const* d_in, const int* in_sizes, int n_in,
                              void* d_out, int out_size)
{
    const float* x       = (const float*)d_in[0];
    const float* qkv_w   = (const float*)d_in[1];
    const float* qkv_b   = (const float*)d_in[2];
    const float* pos_enc = (const float*)d_in[3];
    const float* dwc_w   = (const float*)d_in[4];
    const float* dwc_b   = (const float*)d_in[5];
    const float* proj_w  = (const float*)d_in[6];
    const float* proj_b  = (const float*)d_in[7];
    float* out = (float*)d_out;

    cudaFuncSetAttribute(attn_kernel,
                         cudaFuncAttributeMaxDynamicSharedMemorySize, SMEM_BYTES);

    __half* ae; cudaGetSymbolAddress((void**)&ae, g_ae);
    __half* we; cudaGetSymbolAddress((void**)&we, g_we);
    __half* pe; cudaGetSymbolAddress((void**)&pe, g_pe);

    // 0) conversions: x -> [hi|lo], qkv_w/proj_w -> [hi|hi]
    {
        int nq = MTOT * DIMC / 4;
        cvt_A_ext<<<(nq + 255) / 256, 256>>>(x, ae, nq);
        int nw = 3 * DIMC * DIMC / 4;
        cvt_W_ext<<<(nw + 255) / 256, 256>>>(qkv_w, we, nw);
        int np = DIMC * DIMC / 4;
        cvt_W_ext<<<(np + 255) / 256, 256>>>(proj_w, pe, np);
    }

    // 1) qkv GEMM (fp16 TC) + fused epilogue -> g_q/g_k/g_v
    gemm_f16<0><<<dim3((3 * DIMC) / 128, MTOT / 128), 256>>>(
        ae, we, qkv_b, pos_enc, nullptr);

    // 2) fused linear attention + depthwise conv -> y_ext (reuses g_ae)
    attn_kernel<<<BHTOT, 256, SMEM_BYTES>>>(dwc_w, dwc_b);

    // 3) proj GEMM (fp16 TC) -> out
    gemm_f16<1><<<dim3(DIMC / 128, MTOT / 128), 256>>>(
        ae, pe, proj_b, nullptr, out);
}